// round 15
// baseline (speedup 1.0000x reference)
#include <cuda_runtime.h>
#include <cuda_bf16.h>
#include <cuda_fp16.h>
#include <math.h>
#include <stdint.h>

#define NLEV   24
#define TSIZE  (1u << 19)
#define DH     64
#define DOUT_P 36          // 33 padded to 36 for float4
#define BLK    128
#define EBLK   256
#define N_CAP  (1u << 20)

// ---- kernel B shared memory layout (float units) ----
#define OFF_W1    0                    // 48*64   = 3072
#define OFF_W2    (OFF_W1 + 48*64)     // 64*64   = 4096
#define OFF_W3    (OFF_W2 + 64*64)     // 64*36   = 2304
#define OFF_B1    (OFF_W3 + 64*DOUT_P) // 64
#define OFF_B2    (OFF_B1 + 64)        // 64
#define OFF_B3    (OFF_B2 + 64)        // 36
#define OFF_STAGE (OFF_B3 + DOUT_P)    // half2 stage: 64*128 halfs = 4096 floats
#define SMEM_FLOATS (OFF_STAGE + (DH*BLK)/2)
#define SMEM_BYTES  (SMEM_FLOATS * 4)

#define SC_UP   4096.0f        // 2^12, exact
#define SC_DN   (1.0f/4096.0f)

struct ResArr { float r[NLEV]; };

// scratch: enc[level][point] as float2, coalesced across lanes
__device__ float2 g_enc[(size_t)NLEV * N_CAP];

// ======================= Kernel A: hash encode =======================
__global__ __launch_bounds__(EBLK, 4)
void ngp_encode_kernel(const float* __restrict__ points,
                       const float* __restrict__ bb,
                       const float* __restrict__ table,   // [L, T, 2]
                       int n, ResArr res)
{
    const int i = blockIdx.x * EBLK + threadIdx.x;
    if (i >= n) return;

    float x = fminf(fmaxf(points[3*i+0] / bb[0] + 0.5f, 0.0f), 1.0f);
    float y = fminf(fmaxf(points[3*i+1] / bb[1] + 0.5f, 0.0f), 1.0f);
    float z = fminf(fmaxf(points[3*i+2] / bb[2] + 0.5f, 0.0f), 1.0f);

    const uint32_t m = TSIZE - 1u;
    const float2* tbl2 = reinterpret_cast<const float2*>(table);

    #pragma unroll 2
    for (int l = 0; l < NLEV; l++) {
        const float r = res.r[l];
        float px = x * r, py = y * r, pz = z * r;
        float fx = floorf(px), fy = floorf(py), fz = floorf(pz);
        float wx = px - fx, wy = py - fy, wz = pz - fz;
        uint32_t ix = (uint32_t)fx, iy = (uint32_t)fy, iz = (uint32_t)fz;
        uint32_t hy0 = iy * 2654435761u, hy1 = hy0 + 2654435761u;
        uint32_t hz0 = iz * 805459861u,  hz1 = hz0 + 805459861u;
        uint32_t hx0 = ix, hx1 = ix + 1u;

        const float2* tl = tbl2 + (size_t)l * TSIZE;
        float2 f000 = __ldg(tl + ((hx0 ^ hy0 ^ hz0) & m));
        float2 f100 = __ldg(tl + ((hx1 ^ hy0 ^ hz0) & m));
        float2 f010 = __ldg(tl + ((hx0 ^ hy1 ^ hz0) & m));
        float2 f110 = __ldg(tl + ((hx1 ^ hy1 ^ hz0) & m));
        float2 f001 = __ldg(tl + ((hx0 ^ hy0 ^ hz1) & m));
        float2 f101 = __ldg(tl + ((hx1 ^ hy0 ^ hz1) & m));
        float2 f011 = __ldg(tl + ((hx0 ^ hy1 ^ hz1) & m));
        float2 f111 = __ldg(tl + ((hx1 ^ hy1 ^ hz1) & m));

        float wx0 = 1.0f - wx, wy0 = 1.0f - wy, wz0 = 1.0f - wz;
        float w00 = wx0 * wy0, w10 = wx * wy0, w01 = wx0 * wy, w11 = wx * wy;

        float e0 = wz0 * (w00*f000.x + w10*f100.x + w01*f010.x + w11*f110.x)
                 + wz  * (w00*f001.x + w10*f101.x + w01*f011.x + w11*f111.x);
        float e1 = wz0 * (w00*f000.y + w10*f100.y + w01*f010.y + w11*f110.y)
                 + wz  * (w00*f001.y + w10*f101.y + w01*f011.y + w11*f111.y);

        g_enc[(size_t)l * n + i] = make_float2(e0, e1);
    }
}

// ======================= Kernel B: MLP =======================
__global__ __launch_bounds__(BLK, 4)
void ngp_mlp_kernel(const float* __restrict__ w1, const float* __restrict__ b1,
                    const float* __restrict__ w2, const float* __restrict__ b2,
                    const float* __restrict__ w3, const float* __restrict__ b3,
                    float* __restrict__ out, int n)
{
    extern __shared__ float smem[];
    float* s_w1 = smem + OFF_W1;
    float* s_w2 = smem + OFF_W2;
    float* s_w3 = smem + OFF_W3;
    float* s_b1 = smem + OFF_B1;
    float* s_b2 = smem + OFF_B2;
    float* s_b3 = smem + OFF_B3;
    __half2* s_st = reinterpret_cast<__half2*>(smem + OFF_STAGE);

    const int tid = threadIdx.x;

    for (int idx = tid; idx < 48*64; idx += BLK) s_w1[idx] = w1[idx];
    for (int idx = tid; idx < 64*64; idx += BLK) s_w2[idx] = w2[idx];
    for (int idx = tid; idx < 64*DOUT_P; idx += BLK) {
        int r_ = idx / DOUT_P, c = idx % DOUT_P;
        s_w3[idx] = (c < 33) ? w3[r_*33 + c] : 0.0f;
    }
    for (int idx = tid; idx < 64; idx += BLK) { s_b1[idx] = b1[idx]; s_b2[idx] = b2[idx]; }
    for (int idx = tid; idx < DOUT_P; idx += BLK) s_b3[idx] = (idx < 33) ? b3[idx] : 0.0f;
    __syncthreads();

    const int i = blockIdx.x * BLK + tid;
    if (i >= n) return;

    // --- layer 1 from scratch enc ---
    float h1[DH];
    #pragma unroll
    for (int j = 0; j < DH; j++) h1[j] = s_b1[j];

    #pragma unroll 4
    for (int l = 0; l < NLEV; l++) {
        float2 e = __ldg(&g_enc[(size_t)l * n + i]);
        const float4* r0 = reinterpret_cast<const float4*>(s_w1 + (2*l)   * DH);
        const float4* r1 = reinterpret_cast<const float4*>(s_w1 + (2*l+1) * DH);
        #pragma unroll
        for (int j = 0; j < DH/4; j++) {
            float4 a = r0[j], b = r1[j];
            h1[4*j+0] += e.x * a.x + e.y * b.x;
            h1[4*j+1] += e.x * a.y + e.y * b.y;
            h1[4*j+2] += e.x * a.z + e.y * b.z;
            h1[4*j+3] += e.x * a.w + e.y * b.w;
        }
    }

    // stage relu(h1) in smem as scaled half2 ([k/2][tid], conflict-free)
    #pragma unroll
    for (int k2 = 0; k2 < DH/2; k2++) {
        float a0 = fmaxf(h1[2*k2+0], 0.0f) * SC_UP;
        float a1 = fmaxf(h1[2*k2+1], 0.0f) * SC_UP;
        s_st[k2*BLK + tid] = __floats2half2_rn(a0, a1);
    }

    // --- layer 2 ---
    float h2[DH];
    #pragma unroll
    for (int j = 0; j < DH; j++) h2[j] = s_b2[j];
    #pragma unroll 4
    for (int k2 = 0; k2 < DH/2; k2++) {
        float2 aa = __half22float2(s_st[k2*BLK + tid]);
        float a0 = aa.x * SC_DN, a1 = aa.y * SC_DN;
        const float4* r0 = reinterpret_cast<const float4*>(s_w2 + (2*k2)   * DH);
        const float4* r1 = reinterpret_cast<const float4*>(s_w2 + (2*k2+1) * DH);
        #pragma unroll
        for (int j = 0; j < DH/4; j++) {
            float4 a = r0[j], b = r1[j];
            h2[4*j+0] += a0 * a.x + a1 * b.x;
            h2[4*j+1] += a0 * a.y + a1 * b.y;
            h2[4*j+2] += a0 * a.z + a1 * b.z;
            h2[4*j+3] += a0 * a.w + a1 * b.w;
        }
    }

    // stage relu(h2) (reuse buffer; each thread touches only its own column)
    #pragma unroll
    for (int k2 = 0; k2 < DH/2; k2++) {
        float a0 = fmaxf(h2[2*k2+0], 0.0f) * SC_UP;
        float a1 = fmaxf(h2[2*k2+1], 0.0f) * SC_UP;
        s_st[k2*BLK + tid] = __floats2half2_rn(a0, a1);
    }

    // --- layer 3 (padded 36) ---
    float o[DOUT_P];
    #pragma unroll
    for (int j = 0; j < DOUT_P; j++) o[j] = s_b3[j];
    #pragma unroll 4
    for (int k2 = 0; k2 < DH/2; k2++) {
        float2 aa = __half22float2(s_st[k2*BLK + tid]);
        float a0 = aa.x * SC_DN, a1 = aa.y * SC_DN;
        const float4* r0 = reinterpret_cast<const float4*>(s_w3 + (2*k2)   * DOUT_P);
        const float4* r1 = reinterpret_cast<const float4*>(s_w3 + (2*k2+1) * DOUT_P);
        #pragma unroll
        for (int j = 0; j < DOUT_P/4; j++) {
            float4 a = r0[j], b = r1[j];
            o[4*j+0] += a0 * a.x + a1 * b.x;
            o[4*j+1] += a0 * a.y + a1 * b.y;
            o[4*j+2] += a0 * a.z + a1 * b.z;
            o[4*j+3] += a0 * a.w + a1 * b.w;
        }
    }

    // outputs: d_out = [density (n), geom_feat (n*32)]
    float o0 = o[0];
    out[i] = fmaxf(o0, 0.0f) + log1pf(expf(-fabsf(o0)));   // stable softplus

    float4* g = reinterpret_cast<float4*>(out + (size_t)n + (size_t)i * 32);
    #pragma unroll
    for (int j = 0; j < 8; j++)
        g[j] = make_float4(o[1+4*j], o[2+4*j], o[3+4*j], o[4+4*j]);
}

extern "C" void kernel_launch(void* const* d_in, const int* in_sizes, int n_in,
                              void* d_out, int out_size)
{
    const float* points = (const float*)d_in[0];
    const float* bb     = (const float*)d_in[1];
    const float* table  = (const float*)d_in[2];
    const float* w1     = (const float*)d_in[3];
    const float* b1     = (const float*)d_in[4];
    const float* w2     = (const float*)d_in[5];
    const float* b2     = (const float*)d_in[6];
    const float* w3     = (const float*)d_in[7];
    const float* b3     = (const float*)d_in[8];
    float* out          = (float*)d_out;

    const int n = in_sizes[0] / 3;
    if (n <= 0 || n > (int)N_CAP) return;

    // resolutions, bit-exact vs numpy float64 path
    ResArr res;
    {
        double bexp = exp(log(2048.0 / 16.0) / 23.0);
        for (int l = 0; l < NLEV; l++)
            res.r[l] = (float)floor(16.0 * pow(bexp, (double)l));
    }

    cudaFuncSetAttribute(ngp_mlp_kernel,
                         cudaFuncAttributeMaxDynamicSharedMemorySize, SMEM_BYTES);

    int eblocks = (n + EBLK - 1) / EBLK;
    ngp_encode_kernel<<<eblocks, EBLK>>>(points, bb, table, n, res);

    int blocks = (n + BLK - 1) / BLK;
    ngp_mlp_kernel<<<blocks, BLK, SMEM_BYTES>>>(w1, b1, w2, b2, w3, b3, out, n);
}

// round 16
// speedup vs baseline: 1.1384x; 1.1384x over previous
#include <cuda_runtime.h>
#include <cuda_bf16.h>
#include <cuda_fp16.h>
#include <math.h>
#include <stdint.h>

#define NLEV   24
#define TSIZE  (1u << 19)
#define DH     64
#define DOUT_P 36          // 33 padded to 36 (= 18 f32x2 pairs, rows 16B-aligned)
#define BLK    128
#define EBLK   256
#define N_CAP  (1u << 20)

// ---- kernel B shared memory layout (float units) ----
#define OFF_W1    0                    // 48*64   = 3072
#define OFF_W2    (OFF_W1 + 48*64)     // 64*64   = 4096
#define OFF_W3    (OFF_W2 + 64*64)     // 64*36   = 2304
#define OFF_B1    (OFF_W3 + 64*DOUT_P) // 64
#define OFF_B2    (OFF_B1 + 64)        // 64
#define OFF_B3    (OFF_B2 + 64)        // 36
#define OFF_STAGE (OFF_B3 + DOUT_P)    // half2 stage: 64*128 halfs = 4096 floats
#define SMEM_FLOATS (OFF_STAGE + (DH*BLK)/2)
#define SMEM_BYTES  (SMEM_FLOATS * 4)

#define SC_UP   4096.0f        // 2^12, exact
#define SC_DN   (1.0f/4096.0f)

struct ResArr { float r[NLEV]; };

// scratch: enc[level][point] as float2, coalesced across lanes
__device__ float2 g_enc[(size_t)NLEV * N_CAP];

// ---- packed f32x2 helpers (SASS FFMA2, PTX-only path) ----
__device__ __forceinline__ unsigned long long pk_bcast(float v) {
    unsigned long long r;
    asm("mov.b64 %0, {%1, %1};" : "=l"(r) : "f"(v));
    return r;
}
__device__ __forceinline__ unsigned long long pk_pair(float x, float y) {
    unsigned long long r;
    asm("mov.b64 %0, {%1, %2};" : "=l"(r) : "f"(x), "f"(y));
    return r;
}
__device__ __forceinline__ float2 unpk(unsigned long long v) {
    float2 f;
    asm("mov.b64 {%0, %1}, %2;" : "=f"(f.x), "=f"(f.y) : "l"(v));
    return f;
}
__device__ __forceinline__ void fma2(unsigned long long& d,
                                     unsigned long long a, unsigned long long b) {
    asm("fma.rn.f32x2 %0, %1, %2, %0;" : "+l"(d) : "l"(a), "l"(b));
}

// ======================= Kernel A: hash encode =======================
__global__ __launch_bounds__(EBLK, 4)
void ngp_encode_kernel(const float* __restrict__ points,
                       const float* __restrict__ bb,
                       const float* __restrict__ table,   // [L, T, 2]
                       int n, ResArr res)
{
    const int i = blockIdx.x * EBLK + threadIdx.x;
    if (i >= n) return;

    float x = fminf(fmaxf(points[3*i+0] / bb[0] + 0.5f, 0.0f), 1.0f);
    float y = fminf(fmaxf(points[3*i+1] / bb[1] + 0.5f, 0.0f), 1.0f);
    float z = fminf(fmaxf(points[3*i+2] / bb[2] + 0.5f, 0.0f), 1.0f);

    const uint32_t m = TSIZE - 1u;
    const float2* tbl2 = reinterpret_cast<const float2*>(table);

    #pragma unroll 2
    for (int l = 0; l < NLEV; l++) {
        const float r = res.r[l];
        float px = x * r, py = y * r, pz = z * r;
        float fx = floorf(px), fy = floorf(py), fz = floorf(pz);
        float wx = px - fx, wy = py - fy, wz = pz - fz;
        uint32_t ix = (uint32_t)fx, iy = (uint32_t)fy, iz = (uint32_t)fz;
        uint32_t hy0 = iy * 2654435761u, hy1 = hy0 + 2654435761u;
        uint32_t hz0 = iz * 805459861u,  hz1 = hz0 + 805459861u;
        uint32_t hx0 = ix, hx1 = ix + 1u;

        const float2* tl = tbl2 + (size_t)l * TSIZE;
        float2 f000 = __ldg(tl + ((hx0 ^ hy0 ^ hz0) & m));
        float2 f100 = __ldg(tl + ((hx1 ^ hy0 ^ hz0) & m));
        float2 f010 = __ldg(tl + ((hx0 ^ hy1 ^ hz0) & m));
        float2 f110 = __ldg(tl + ((hx1 ^ hy1 ^ hz0) & m));
        float2 f001 = __ldg(tl + ((hx0 ^ hy0 ^ hz1) & m));
        float2 f101 = __ldg(tl + ((hx1 ^ hy0 ^ hz1) & m));
        float2 f011 = __ldg(tl + ((hx0 ^ hy1 ^ hz1) & m));
        float2 f111 = __ldg(tl + ((hx1 ^ hy1 ^ hz1) & m));

        float wx0 = 1.0f - wx, wy0 = 1.0f - wy, wz0 = 1.0f - wz;
        float w00 = wx0 * wy0, w10 = wx * wy0, w01 = wx0 * wy, w11 = wx * wy;

        float e0 = wz0 * (w00*f000.x + w10*f100.x + w01*f010.x + w11*f110.x)
                 + wz  * (w00*f001.x + w10*f101.x + w01*f011.x + w11*f111.x);
        float e1 = wz0 * (w00*f000.y + w10*f100.y + w01*f010.y + w11*f110.y)
                 + wz  * (w00*f001.y + w10*f101.y + w01*f011.y + w11*f111.y);

        g_enc[(size_t)l * n + i] = make_float2(e0, e1);
    }
}

// ======================= Kernel B: MLP (packed f32x2) =======================
__global__ __launch_bounds__(BLK, 4)
void ngp_mlp_kernel(const float* __restrict__ w1, const float* __restrict__ b1,
                    const float* __restrict__ w2, const float* __restrict__ b2,
                    const float* __restrict__ w3, const float* __restrict__ b3,
                    float* __restrict__ out, int n)
{
    extern __shared__ float smem[];
    float* s_w1 = smem + OFF_W1;
    float* s_w2 = smem + OFF_W2;
    float* s_w3 = smem + OFF_W3;
    float* s_b1 = smem + OFF_B1;
    float* s_b2 = smem + OFF_B2;
    float* s_b3 = smem + OFF_B3;
    __half2* s_st = reinterpret_cast<__half2*>(smem + OFF_STAGE);

    const int tid = threadIdx.x;

    for (int idx = tid; idx < 48*64; idx += BLK) s_w1[idx] = w1[idx];
    for (int idx = tid; idx < 64*64; idx += BLK) s_w2[idx] = w2[idx];
    for (int idx = tid; idx < 64*DOUT_P; idx += BLK) {
        int r_ = idx / DOUT_P, c = idx % DOUT_P;
        s_w3[idx] = (c < 33) ? w3[r_*33 + c] : 0.0f;
    }
    for (int idx = tid; idx < 64; idx += BLK) { s_b1[idx] = b1[idx]; s_b2[idx] = b2[idx]; }
    for (int idx = tid; idx < DOUT_P; idx += BLK) s_b3[idx] = (idx < 33) ? b3[idx] : 0.0f;
    __syncthreads();

    const int i = blockIdx.x * BLK + tid;
    if (i >= n) return;

    // --- layer 1: acc[j] holds channels (2j, 2j+1) packed ---
    unsigned long long acc[DH/2];
    {
        const float2* bv = reinterpret_cast<const float2*>(s_b1);
        #pragma unroll
        for (int j = 0; j < DH/2; j++) { float2 b = bv[j]; acc[j] = pk_pair(b.x, b.y); }
    }

    #pragma unroll 4
    for (int l = 0; l < NLEV; l++) {
        float2 e = __ldg(&g_enc[(size_t)l * n + i]);
        unsigned long long e0p = pk_bcast(e.x), e1p = pk_bcast(e.y);
        const ulonglong2* r0 = reinterpret_cast<const ulonglong2*>(s_w1 + (2*l)   * DH);
        const ulonglong2* r1 = reinterpret_cast<const ulonglong2*>(s_w1 + (2*l+1) * DH);
        #pragma unroll
        for (int j = 0; j < DH/4; j++) {
            ulonglong2 a = r0[j], b = r1[j];
            fma2(acc[2*j+0], e0p, a.x); fma2(acc[2*j+0], e1p, b.x);
            fma2(acc[2*j+1], e0p, a.y); fma2(acc[2*j+1], e1p, b.y);
        }
    }

    // stage relu(h1) in smem as scaled half2 ([pair][tid], conflict-free)
    #pragma unroll
    for (int j = 0; j < DH/2; j++) {
        float2 h = unpk(acc[j]);
        s_st[j*BLK + tid] = __floats2half2_rn(fmaxf(h.x, 0.0f) * SC_UP,
                                              fmaxf(h.y, 0.0f) * SC_UP);
    }

    // --- layer 2 ---
    {
        const float2* bv = reinterpret_cast<const float2*>(s_b2);
        #pragma unroll
        for (int j = 0; j < DH/2; j++) { float2 b = bv[j]; acc[j] = pk_pair(b.x, b.y); }
    }
    #pragma unroll 4
    for (int k2 = 0; k2 < DH/2; k2++) {
        float2 aa = __half22float2(s_st[k2*BLK + tid]);
        unsigned long long a0p = pk_bcast(aa.x * SC_DN), a1p = pk_bcast(aa.y * SC_DN);
        const ulonglong2* r0 = reinterpret_cast<const ulonglong2*>(s_w2 + (2*k2)   * DH);
        const ulonglong2* r1 = reinterpret_cast<const ulonglong2*>(s_w2 + (2*k2+1) * DH);
        #pragma unroll
        for (int j = 0; j < DH/4; j++) {
            ulonglong2 a = r0[j], b = r1[j];
            fma2(acc[2*j+0], a0p, a.x); fma2(acc[2*j+0], a1p, b.x);
            fma2(acc[2*j+1], a0p, a.y); fma2(acc[2*j+1], a1p, b.y);
        }
    }

    // stage relu(h2) (reuse buffer; each thread touches only its own column)
    #pragma unroll
    for (int j = 0; j < DH/2; j++) {
        float2 h = unpk(acc[j]);
        s_st[j*BLK + tid] = __floats2half2_rn(fmaxf(h.x, 0.0f) * SC_UP,
                                              fmaxf(h.y, 0.0f) * SC_UP);
    }

    // --- layer 3 (36 outputs = 18 pairs; rows are 144B = 9 x 16B aligned) ---
    unsigned long long acc3[DOUT_P/2];
    {
        const float2* bv = reinterpret_cast<const float2*>(s_b3);
        #pragma unroll
        for (int j = 0; j < DOUT_P/2; j++) { float2 b = bv[j]; acc3[j] = pk_pair(b.x, b.y); }
    }
    #pragma unroll 4
    for (int k2 = 0; k2 < DH/2; k2++) {
        float2 aa = __half22float2(s_st[k2*BLK + tid]);
        unsigned long long a0p = pk_bcast(aa.x * SC_DN), a1p = pk_bcast(aa.y * SC_DN);
        const ulonglong2* r0 = reinterpret_cast<const ulonglong2*>(s_w3 + (2*k2)   * DOUT_P);
        const ulonglong2* r1 = reinterpret_cast<const ulonglong2*>(s_w3 + (2*k2+1) * DOUT_P);
        #pragma unroll
        for (int j = 0; j < DOUT_P/4; j++) {
            ulonglong2 a = r0[j], b = r1[j];
            fma2(acc3[2*j+0], a0p, a.x); fma2(acc3[2*j+0], a1p, b.x);
            fma2(acc3[2*j+1], a0p, a.y); fma2(acc3[2*j+1], a1p, b.y);
        }
    }

    // unpack outputs
    float o[DOUT_P];
    #pragma unroll
    for (int j = 0; j < DOUT_P/2; j++) {
        float2 v = unpk(acc3[j]);
        o[2*j+0] = v.x; o[2*j+1] = v.y;
    }

    // outputs: d_out = [density (n), geom_feat (n*32)]
    float o0 = o[0];
    out[i] = fmaxf(o0, 0.0f) + log1pf(expf(-fabsf(o0)));   // stable softplus

    float4* g = reinterpret_cast<float4*>(out + (size_t)n + (size_t)i * 32);
    #pragma unroll
    for (int j = 0; j < 8; j++)
        g[j] = make_float4(o[1+4*j], o[2+4*j], o[3+4*j], o[4+4*j]);
}

extern "C" void kernel_launch(void* const* d_in, const int* in_sizes, int n_in,
                              void* d_out, int out_size)
{
    const float* points = (const float*)d_in[0];
    const float* bb     = (const float*)d_in[1];
    const float* table  = (const float*)d_in[2];
    const float* w1     = (const float*)d_in[3];
    const float* b1     = (const float*)d_in[4];
    const float* w2     = (const float*)d_in[5];
    const float* b2     = (const float*)d_in[6];
    const float* w3     = (const float*)d_in[7];
    const float* b3     = (const float*)d_in[8];
    float* out          = (float*)d_out;

    const int n = in_sizes[0] / 3;
    if (n <= 0 || n > (int)N_CAP) return;

    // resolutions, bit-exact vs numpy float64 path
    ResArr res;
    {
        double bexp = exp(log(2048.0 / 16.0) / 23.0);
        for (int l = 0; l < NLEV; l++)
            res.r[l] = (float)floor(16.0 * pow(bexp, (double)l));
    }

    cudaFuncSetAttribute(ngp_mlp_kernel,
                         cudaFuncAttributeMaxDynamicSharedMemorySize, SMEM_BYTES);

    int eblocks = (n + EBLK - 1) / EBLK;
    ngp_encode_kernel<<<eblocks, EBLK>>>(points, bb, table, n, res);

    int blocks = (n + BLK - 1) / BLK;
    ngp_mlp_kernel<<<blocks, BLK, SMEM_BYTES>>>(w1, b1, w2, b2, w3, b3, out, n);
}

// round 17
// speedup vs baseline: 1.2230x; 1.0743x over previous
#include <cuda_runtime.h>
#include <cuda_bf16.h>
#include <cuda_fp16.h>
#include <math.h>
#include <stdint.h>

#define NLEV   24
#define TSIZE  (1u << 19)
#define DH     64
#define DOUT_P 36          // 33 padded to 36 (= 18 f32x2 pairs, rows 16B-aligned)
#define BLK    128
#define PPT    2           // points per thread (MLP)
#define PTS    (BLK*PPT)   // 256 points per block
#define EBLK   256
#define N_CAP  (1u << 20)

// ---- kernel B shared memory layout (float units) ----
#define OFF_W1    0                    // 48*64   = 3072
#define OFF_W2    (OFF_W1 + 48*64)     // 64*64   = 4096
#define OFF_W3    (OFF_W2 + 64*64)     // 64*36   = 2304
#define OFF_B1    (OFF_W3 + 64*DOUT_P) // 64
#define OFF_B2    (OFF_B1 + 64)        // 64
#define OFF_B3    (OFF_B2 + 64)        // 36
#define OFF_STAGE (OFF_B3 + DOUT_P)    // half2 stage: 32 pairs x 256 slots = 8192 floats
#define SMEM_FLOATS (OFF_STAGE + (DH/2)*PTS)
#define SMEM_BYTES  (SMEM_FLOATS * 4)

#define SC_UP   4096.0f        // 2^12, exact
#define SC_DN   (1.0f/4096.0f)

struct ResArr { float r[NLEV]; };

// scratch: enc[level][point] as float2, coalesced across lanes
__device__ float2 g_enc[(size_t)NLEV * N_CAP];

// ---- packed f32x2 helpers (SASS FFMA2, PTX-only path) ----
__device__ __forceinline__ unsigned long long pk_bcast(float v) {
    unsigned long long r;
    asm("mov.b64 %0, {%1, %1};" : "=l"(r) : "f"(v));
    return r;
}
__device__ __forceinline__ unsigned long long pk_pair(float x, float y) {
    unsigned long long r;
    asm("mov.b64 %0, {%1, %2};" : "=l"(r) : "f"(x), "f"(y));
    return r;
}
__device__ __forceinline__ float2 unpk(unsigned long long v) {
    float2 f;
    asm("mov.b64 {%0, %1}, %2;" : "=f"(f.x), "=f"(f.y) : "l"(v));
    return f;
}
__device__ __forceinline__ void fma2(unsigned long long& d,
                                     unsigned long long a, unsigned long long b) {
    asm("fma.rn.f32x2 %0, %1, %2, %0;" : "+l"(d) : "l"(a), "l"(b));
}

// ======================= Kernel A: hash encode =======================
__global__ __launch_bounds__(EBLK, 4)
void ngp_encode_kernel(const float* __restrict__ points,
                       const float* __restrict__ bb,
                       const float* __restrict__ table,   // [L, T, 2]
                       int n, ResArr res)
{
    const int i = blockIdx.x * EBLK + threadIdx.x;
    if (i >= n) return;

    float x = fminf(fmaxf(points[3*i+0] / bb[0] + 0.5f, 0.0f), 1.0f);
    float y = fminf(fmaxf(points[3*i+1] / bb[1] + 0.5f, 0.0f), 1.0f);
    float z = fminf(fmaxf(points[3*i+2] / bb[2] + 0.5f, 0.0f), 1.0f);

    const uint32_t m = TSIZE - 1u;
    const float2* tbl2 = reinterpret_cast<const float2*>(table);

    #pragma unroll 2
    for (int l = 0; l < NLEV; l++) {
        const float r = res.r[l];
        float px = x * r, py = y * r, pz = z * r;
        float fx = floorf(px), fy = floorf(py), fz = floorf(pz);
        float wx = px - fx, wy = py - fy, wz = pz - fz;
        uint32_t ix = (uint32_t)fx, iy = (uint32_t)fy, iz = (uint32_t)fz;
        uint32_t hy0 = iy * 2654435761u, hy1 = hy0 + 2654435761u;
        uint32_t hz0 = iz * 805459861u,  hz1 = hz0 + 805459861u;
        uint32_t hx0 = ix, hx1 = ix + 1u;

        const float2* tl = tbl2 + (size_t)l * TSIZE;
        float2 f000 = __ldg(tl + ((hx0 ^ hy0 ^ hz0) & m));
        float2 f100 = __ldg(tl + ((hx1 ^ hy0 ^ hz0) & m));
        float2 f010 = __ldg(tl + ((hx0 ^ hy1 ^ hz0) & m));
        float2 f110 = __ldg(tl + ((hx1 ^ hy1 ^ hz0) & m));
        float2 f001 = __ldg(tl + ((hx0 ^ hy0 ^ hz1) & m));
        float2 f101 = __ldg(tl + ((hx1 ^ hy0 ^ hz1) & m));
        float2 f011 = __ldg(tl + ((hx0 ^ hy1 ^ hz1) & m));
        float2 f111 = __ldg(tl + ((hx1 ^ hy1 ^ hz1) & m));

        float wx0 = 1.0f - wx, wy0 = 1.0f - wy, wz0 = 1.0f - wz;
        float w00 = wx0 * wy0, w10 = wx * wy0, w01 = wx0 * wy, w11 = wx * wy;

        float e0 = wz0 * (w00*f000.x + w10*f100.x + w01*f010.x + w11*f110.x)
                 + wz  * (w00*f001.x + w10*f101.x + w01*f011.x + w11*f111.x);
        float e1 = wz0 * (w00*f000.y + w10*f100.y + w01*f010.y + w11*f110.y)
                 + wz  * (w00*f001.y + w10*f101.y + w01*f011.y + w11*f111.y);

        g_enc[(size_t)l * n + i] = make_float2(e0, e1);
    }
}

// ======================= Kernel B: MLP (f32x2, 2 points/thread) =======================
__global__ __launch_bounds__(BLK, 3)
void ngp_mlp_kernel(const float* __restrict__ w1, const float* __restrict__ b1,
                    const float* __restrict__ w2, const float* __restrict__ b2,
                    const float* __restrict__ w3, const float* __restrict__ b3,
                    float* __restrict__ out, int n)
{
    extern __shared__ float smem[];
    float* s_w1 = smem + OFF_W1;
    float* s_w2 = smem + OFF_W2;
    float* s_w3 = smem + OFF_W3;
    float* s_b1 = smem + OFF_B1;
    float* s_b2 = smem + OFF_B2;
    float* s_b3 = smem + OFF_B3;
    __half2* s_st = reinterpret_cast<__half2*>(smem + OFF_STAGE);

    const int tid = threadIdx.x;

    for (int idx = tid; idx < 48*64; idx += BLK) s_w1[idx] = w1[idx];
    for (int idx = tid; idx < 64*64; idx += BLK) s_w2[idx] = w2[idx];
    for (int idx = tid; idx < 64*DOUT_P; idx += BLK) {
        int r_ = idx / DOUT_P, c = idx % DOUT_P;
        s_w3[idx] = (c < 33) ? w3[r_*33 + c] : 0.0f;
    }
    for (int idx = tid; idx < 64; idx += BLK) { s_b1[idx] = b1[idx]; s_b2[idx] = b2[idx]; }
    for (int idx = tid; idx < DOUT_P; idx += BLK) s_b3[idx] = (idx < 33) ? b3[idx] : 0.0f;
    __syncthreads();

    const int iA = blockIdx.x * PTS + tid;          // point A
    const int iB = iA + BLK;                        // point B
    if (iA >= n) return;
    const bool hasB = (iB < n);
    const int iBc = hasB ? iB : iA;                 // clamped for loads

    // --- layer 1: acc*[j] holds channels (2j, 2j+1) packed, one set per point ---
    unsigned long long accA[DH/2], accB[DH/2];
    {
        const float2* bv = reinterpret_cast<const float2*>(s_b1);
        #pragma unroll
        for (int j = 0; j < DH/2; j++) {
            float2 b = bv[j];
            unsigned long long p = pk_pair(b.x, b.y);
            accA[j] = p; accB[j] = p;
        }
    }

    #pragma unroll 2
    for (int l = 0; l < NLEV; l++) {
        float2 eA = __ldg(&g_enc[(size_t)l * n + iA]);
        float2 eB = __ldg(&g_enc[(size_t)l * n + iBc]);
        unsigned long long eA0 = pk_bcast(eA.x), eA1 = pk_bcast(eA.y);
        unsigned long long eB0 = pk_bcast(eB.x), eB1 = pk_bcast(eB.y);
        const ulonglong2* r0 = reinterpret_cast<const ulonglong2*>(s_w1 + (2*l)   * DH);
        const ulonglong2* r1 = reinterpret_cast<const ulonglong2*>(s_w1 + (2*l+1) * DH);
        #pragma unroll
        for (int j = 0; j < DH/4; j++) {
            ulonglong2 a = r0[j], b = r1[j];
            fma2(accA[2*j+0], eA0, a.x); fma2(accA[2*j+0], eA1, b.x);
            fma2(accA[2*j+1], eA0, a.y); fma2(accA[2*j+1], eA1, b.y);
            fma2(accB[2*j+0], eB0, a.x); fma2(accB[2*j+0], eB1, b.x);
            fma2(accB[2*j+1], eB0, a.y); fma2(accB[2*j+1], eB1, b.y);
        }
    }

    // stage relu(h1) as scaled half2: [pair j][slot], slots: A=tid, B=tid+BLK
    #pragma unroll
    for (int j = 0; j < DH/2; j++) {
        float2 hA = unpk(accA[j]);
        float2 hB = unpk(accB[j]);
        s_st[j*PTS + tid]       = __floats2half2_rn(fmaxf(hA.x, 0.0f) * SC_UP,
                                                    fmaxf(hA.y, 0.0f) * SC_UP);
        s_st[j*PTS + tid + BLK] = __floats2half2_rn(fmaxf(hB.x, 0.0f) * SC_UP,
                                                    fmaxf(hB.y, 0.0f) * SC_UP);
    }

    // --- layer 2 ---
    {
        const float2* bv = reinterpret_cast<const float2*>(s_b2);
        #pragma unroll
        for (int j = 0; j < DH/2; j++) {
            float2 b = bv[j];
            unsigned long long p = pk_pair(b.x, b.y);
            accA[j] = p; accB[j] = p;
        }
    }
    #pragma unroll 2
    for (int k2 = 0; k2 < DH/2; k2++) {
        float2 aA = __half22float2(s_st[k2*PTS + tid]);
        float2 aB = __half22float2(s_st[k2*PTS + tid + BLK]);
        unsigned long long aA0 = pk_bcast(aA.x * SC_DN), aA1 = pk_bcast(aA.y * SC_DN);
        unsigned long long aB0 = pk_bcast(aB.x * SC_DN), aB1 = pk_bcast(aB.y * SC_DN);
        const ulonglong2* r0 = reinterpret_cast<const ulonglong2*>(s_w2 + (2*k2)   * DH);
        const ulonglong2* r1 = reinterpret_cast<const ulonglong2*>(s_w2 + (2*k2+1) * DH);
        #pragma unroll
        for (int j = 0; j < DH/4; j++) {
            ulonglong2 a = r0[j], b = r1[j];
            fma2(accA[2*j+0], aA0, a.x); fma2(accA[2*j+0], aA1, b.x);
            fma2(accA[2*j+1], aA0, a.y); fma2(accA[2*j+1], aA1, b.y);
            fma2(accB[2*j+0], aB0, a.x); fma2(accB[2*j+0], aB1, b.x);
            fma2(accB[2*j+1], aB0, a.y); fma2(accB[2*j+1], aB1, b.y);
        }
    }

    // stage relu(h2)
    #pragma unroll
    for (int j = 0; j < DH/2; j++) {
        float2 hA = unpk(accA[j]);
        float2 hB = unpk(accB[j]);
        s_st[j*PTS + tid]       = __floats2half2_rn(fmaxf(hA.x, 0.0f) * SC_UP,
                                                    fmaxf(hA.y, 0.0f) * SC_UP);
        s_st[j*PTS + tid + BLK] = __floats2half2_rn(fmaxf(hB.x, 0.0f) * SC_UP,
                                                    fmaxf(hB.y, 0.0f) * SC_UP);
    }

    // --- layer 3 (36 outputs = 18 pairs; rows 144 B, 16B-aligned) ---
    unsigned long long acc3A[DOUT_P/2], acc3B[DOUT_P/2];
    {
        const float2* bv = reinterpret_cast<const float2*>(s_b3);
        #pragma unroll
        for (int j = 0; j < DOUT_P/2; j++) {
            float2 b = bv[j];
            unsigned long long p = pk_pair(b.x, b.y);
            acc3A[j] = p; acc3B[j] = p;
        }
    }
    #pragma unroll 2
    for (int k2 = 0; k2 < DH/2; k2++) {
        float2 aA = __half22float2(s_st[k2*PTS + tid]);
        float2 aB = __half22float2(s_st[k2*PTS + tid + BLK]);
        unsigned long long aA0 = pk_bcast(aA.x * SC_DN), aA1 = pk_bcast(aA.y * SC_DN);
        unsigned long long aB0 = pk_bcast(aB.x * SC_DN), aB1 = pk_bcast(aB.y * SC_DN);
        const ulonglong2* r0 = reinterpret_cast<const ulonglong2*>(s_w3 + (2*k2)   * DOUT_P);
        const ulonglong2* r1 = reinterpret_cast<const ulonglong2*>(s_w3 + (2*k2+1) * DOUT_P);
        #pragma unroll
        for (int j = 0; j < DOUT_P/4; j++) {
            ulonglong2 a = r0[j], b = r1[j];
            fma2(acc3A[2*j+0], aA0, a.x); fma2(acc3A[2*j+0], aA1, b.x);
            fma2(acc3A[2*j+1], aA0, a.y); fma2(acc3A[2*j+1], aA1, b.y);
            fma2(acc3B[2*j+0], aB0, a.x); fma2(acc3B[2*j+0], aB1, b.x);
            fma2(acc3B[2*j+1], aB0, a.y); fma2(acc3B[2*j+1], aB1, b.y);
        }
    }

    // outputs: d_out = [density (n), geom_feat (n*32)]
    {
        float oA[DOUT_P];
        #pragma unroll
        for (int j = 0; j < DOUT_P/2; j++) {
            float2 v = unpk(acc3A[j]); oA[2*j] = v.x; oA[2*j+1] = v.y;
        }
        float o0 = oA[0];
        out[iA] = fmaxf(o0, 0.0f) + log1pf(expf(-fabsf(o0)));
        float4* g = reinterpret_cast<float4*>(out + (size_t)n + (size_t)iA * 32);
        #pragma unroll
        for (int j = 0; j < 8; j++)
            g[j] = make_float4(oA[1+4*j], oA[2+4*j], oA[3+4*j], oA[4+4*j]);
    }
    if (hasB) {
        float oB[DOUT_P];
        #pragma unroll
        for (int j = 0; j < DOUT_P/2; j++) {
            float2 v = unpk(acc3B[j]); oB[2*j] = v.x; oB[2*j+1] = v.y;
        }
        float o0 = oB[0];
        out[iB] = fmaxf(o0, 0.0f) + log1pf(expf(-fabsf(o0)));
        float4* g = reinterpret_cast<float4*>(out + (size_t)n + (size_t)iB * 32);
        #pragma unroll
        for (int j = 0; j < 8; j++)
            g[j] = make_float4(oB[1+4*j], oB[2+4*j], oB[3+4*j], oB[4+4*j]);
    }
}

extern "C" void kernel_launch(void* const* d_in, const int* in_sizes, int n_in,
                              void* d_out, int out_size)
{
    const float* points = (const float*)d_in[0];
    const float* bb     = (const float*)d_in[1];
    const float* table  = (const float*)d_in[2];
    const float* w1     = (const float*)d_in[3];
    const float* b1     = (const float*)d_in[4];
    const float* w2     = (const float*)d_in[5];
    const float* b2     = (const float*)d_in[6];
    const float* w3     = (const float*)d_in[7];
    const float* b3     = (const float*)d_in[8];
    float* out          = (float*)d_out;

    const int n = in_sizes[0] / 3;
    if (n <= 0 || n > (int)N_CAP) return;

    // resolutions, bit-exact vs numpy float64 path
    ResArr res;
    {
        double bexp = exp(log(2048.0 / 16.0) / 23.0);
        for (int l = 0; l < NLEV; l++)
            res.r[l] = (float)floor(16.0 * pow(bexp, (double)l));
    }

    cudaFuncSetAttribute(ngp_mlp_kernel,
                         cudaFuncAttributeMaxDynamicSharedMemorySize, SMEM_BYTES);

    int eblocks = (n + EBLK - 1) / EBLK;
    ngp_encode_kernel<<<eblocks, EBLK>>>(points, bb, table, n, res);

    int blocks = (n + PTS - 1) / PTS;
    ngp_mlp_kernel<<<blocks, BLK, SMEM_BYTES>>>(w1, b1, w2, b2, w3, b3, out, n);
}